// round 2
// baseline (speedup 1.0000x reference)
#include <cuda_runtime.h>
#include <cuda_bf16.h>

#define BATCH  64
#define SEQ    256
#define EMBED  512
#define HIDDEN 1024
#define G4     (4 * HIDDEN)          // 4096
#define BT     (BATCH * SEQ)         // 16384
#define KSPLIT 8

// -------- scratch (device globals; no allocation allowed) --------
__device__ float g_pre [(size_t)BT * G4];          // 268 MB: x@W_ih^T + b_ih + b_hh
__device__ float g_part[(size_t)KSPLIT * BATCH * G4]; // 8 MB: K-split partials of h@W_hh^T
__device__ float g_h   [BATCH * HIDDEN];
__device__ float g_c   [BATCH * HIDDEN];
__device__ float g_hist[(size_t)BT * HIDDEN];      // 67 MB: all h_t for the final fc GEMM

// ---------------------------------------------------------------------------
// Generic NT SGEMM: C[M,N] = A[M,K] * B[N,K]^T (+ bias1 + bias2)
// Block tile 64(m) x 256(n), 256 threads, 8x8 micro-tile, BK=16.
// blockIdx.z = K-split chunk; C += z*czstride, K range [z*kchunk, (z+1)*kchunk).
// Requires: M % 64 == 0, N % 256 == 0, kchunk % 16 == 0, lda/ldb % 4 == 0.
// ---------------------------------------------------------------------------
__global__ __launch_bounds__(256, 2) void sgemm_nt_kernel(
    const float* __restrict__ A, int lda,
    const float* __restrict__ B, int ldb,
    float* __restrict__ C, int ldc,
    int kchunk, long long czstride,
    const float* __restrict__ bias1, const float* __restrict__ bias2)
{
    __shared__ float hs[16][68];    // A chunk transposed: hs[k][m], padded
    __shared__ float ws[16][260];   // B chunk transposed: ws[k][n], padded

    const int m0 = blockIdx.x * 64;
    const int n0 = blockIdx.y * 256;
    const int kstart = blockIdx.z * kchunk;
    C += (long long)blockIdx.z * czstride;

    const int tid = threadIdx.x;
    const int tx = tid & 31;    // 32 n-lanes (each owns n = 4*tx..+3 and 128+4*tx..+3)
    const int ty = tid >> 5;    // 8 m-groups (each owns m = 8*ty..+7)

    float acc[8][8];
#pragma unroll
    for (int i = 0; i < 8; i++)
#pragma unroll
        for (int j = 0; j < 8; j++) acc[i][j] = 0.f;

    const int am = tid >> 2;          // 0..63
    const int ak = (tid & 3) * 4;     // 0,4,8,12
    const float* Aptr = A + (size_t)(m0 + am) * lda + kstart + ak;
    const float* Bptr = B + (size_t)(n0 + tid) * ldb + kstart;

    for (int kc = 0; kc < kchunk; kc += 16) {
        // A tile: 64x16, one float4 per thread
        float4 av = *(const float4*)(Aptr + kc);
        hs[ak + 0][am] = av.x; hs[ak + 1][am] = av.y;
        hs[ak + 2][am] = av.z; hs[ak + 3][am] = av.w;
        // B tile: 256x16, four float4 per thread (one n-row each)
#pragma unroll
        for (int q = 0; q < 4; q++) {
            float4 bv = *(const float4*)(Bptr + kc + q * 4);
            ws[q * 4 + 0][tid] = bv.x; ws[q * 4 + 1][tid] = bv.y;
            ws[q * 4 + 2][tid] = bv.z; ws[q * 4 + 3][tid] = bv.w;
        }
        __syncthreads();
#pragma unroll
        for (int k = 0; k < 16; k++) {
            float4 a0 = *(const float4*)&hs[k][ty * 8];
            float4 a1 = *(const float4*)&hs[k][ty * 8 + 4];
            float4 b0 = *(const float4*)&ws[k][tx * 4];
            float4 b1 = *(const float4*)&ws[k][128 + tx * 4];
            float amr[8] = {a0.x, a0.y, a0.z, a0.w, a1.x, a1.y, a1.z, a1.w};
            float bnr[8] = {b0.x, b0.y, b0.z, b0.w, b1.x, b1.y, b1.z, b1.w};
#pragma unroll
            for (int mi = 0; mi < 8; mi++)
#pragma unroll
                for (int nj = 0; nj < 8; nj++)
                    acc[mi][nj] += amr[mi] * bnr[nj];
        }
        __syncthreads();
    }

    // epilogue: optional biases, vectorized stores
    float bv0[4] = {0.f, 0.f, 0.f, 0.f}, bv1[4] = {0.f, 0.f, 0.f, 0.f};
    if (bias1) {
#pragma unroll
        for (int j = 0; j < 4; j++) {
            bv0[j] += bias1[n0 + tx * 4 + j];
            bv1[j] += bias1[n0 + 128 + tx * 4 + j];
        }
    }
    if (bias2) {
#pragma unroll
        for (int j = 0; j < 4; j++) {
            bv0[j] += bias2[n0 + tx * 4 + j];
            bv1[j] += bias2[n0 + 128 + tx * 4 + j];
        }
    }
#pragma unroll
    for (int mi = 0; mi < 8; mi++) {
        float* crow = C + (size_t)(m0 + ty * 8 + mi) * ldc;
        float4 o0, o1;
        o0.x = acc[mi][0] + bv0[0]; o0.y = acc[mi][1] + bv0[1];
        o0.z = acc[mi][2] + bv0[2]; o0.w = acc[mi][3] + bv0[3];
        o1.x = acc[mi][4] + bv1[0]; o1.y = acc[mi][5] + bv1[1];
        o1.z = acc[mi][6] + bv1[2]; o1.w = acc[mi][7] + bv1[3];
        *(float4*)(crow + n0 + tx * 4)       = o0;
        *(float4*)(crow + n0 + 128 + tx * 4) = o1;
    }
}

// ---------------------------------------------------------------------------
// Per-step: gather K-split partials + precomputed input gates, apply LSTM cell.
// 65536 threads, one per (b, u).
// ---------------------------------------------------------------------------
__global__ void lstm_update_kernel(int t)
{
    const int idx = blockIdx.x * blockDim.x + threadIdx.x;
    const int b = idx >> 10;
    const int u = idx & 1023;
    const size_t m = (size_t)b * SEQ + t;

    const float* prer = g_pre + m * G4;
    float gi = prer[u];
    float gf = prer[u + HIDDEN];
    float gg = prer[u + 2 * HIDDEN];
    float go = prer[u + 3 * HIDDEN];
#pragma unroll
    for (int ks = 0; ks < KSPLIT; ks++) {
        const float* p = g_part + (size_t)ks * BATCH * G4 + (size_t)b * G4;
        gi += p[u];
        gf += p[u + HIDDEN];
        gg += p[u + 2 * HIDDEN];
        go += p[u + 3 * HIDDEN];
    }
    float cc = g_c[idx];
    float i_ = 1.f / (1.f + __expf(-gi));
    float f_ = 1.f / (1.f + __expf(-gf));
    float gv = tanhf(gg);
    float o_ = 1.f / (1.f + __expf(-go));
    cc = f_ * cc + i_ * gv;
    float hh = o_ * tanhf(cc);
    g_c[idx] = cc;
    g_h[idx] = hh;
    g_hist[m * HIDDEN + u] = hh;
}

__global__ void init_state_kernel()
{
    const int idx = blockIdx.x * blockDim.x + threadIdx.x;
    g_h[idx] = 0.f;
    g_c[idx] = 0.f;
}

// ---------------------------------------------------------------------------
extern "C" void kernel_launch(void* const* d_in, const int* in_sizes, int n_in,
                              void* d_out, int out_size)
{
    const float* emb  = (const float*)d_in[0];  // [64, 256, 512]
    const float* W_ih = (const float*)d_in[1];  // [4096, 512]
    const float* W_hh = (const float*)d_in[2];  // [4096, 1024]
    const float* b_ih = (const float*)d_in[3];  // [4096]
    const float* b_hh = (const float*)d_in[4];  // [4096]
    const float* W_fc = (const float*)d_in[5];  // [1024, 1024]
    const float* b_fc = (const float*)d_in[6];  // [1024]
    float* out = (float*)d_out;                 // [64, 256, 1024]

    float *pre, *part, *h, *c, *hist;
    cudaGetSymbolAddress((void**)&pre,  g_pre);
    cudaGetSymbolAddress((void**)&part, g_part);
    cudaGetSymbolAddress((void**)&h,    g_h);
    cudaGetSymbolAddress((void**)&c,    g_c);
    cudaGetSymbolAddress((void**)&hist, g_hist);

    // 1) Prepass: g_pre[m, 4H] = emb[m, :] @ W_ih^T + b_ih + b_hh   (m = b*SEQ + t)
    sgemm_nt_kernel<<<dim3(BT / 64, G4 / 256, 1), 256>>>(
        emb, EMBED, W_ih, EMBED, pre, G4, EMBED, 0, b_ih, b_hh);

    // 2) h = c = 0
    init_state_kernel<<<64, 1024>>>();

    // 3) Sequential recurrence: per step, K-split GEMM + fused gather/cell update
    for (int t = 0; t < SEQ; t++) {
        sgemm_nt_kernel<<<dim3(1, G4 / 256, KSPLIT), 256>>>(
            h, HIDDEN, W_hh, HIDDEN, part, G4,
            HIDDEN / KSPLIT, (long long)BATCH * G4, nullptr, nullptr);
        lstm_update_kernel<<<64, 1024>>>(t);
    }

    // 4) Output projection: out[m, :] = hist[m, :] @ W_fc^T + b_fc
    sgemm_nt_kernel<<<dim3(BT / 64, HIDDEN / 256, 1), 256>>>(
        hist, HIDDEN, W_fc, HIDDEN, out, HIDDEN, HIDDEN, 0, b_fc, nullptr);
}

// round 3
// speedup vs baseline: 1.9001x; 1.9001x over previous
#include <cuda_runtime.h>

#define BATCH  64
#define SEQ    256
#define EMBED  512
#define HIDDEN 1024
#define G4     4096
#define BT     (BATCH * SEQ)
#define NCTA   128

// ---------------- scratch ----------------
__device__ float g_pre[(size_t)BT * G4];                 // [t][b][4H]  (t-major)
__device__ float g_hh [(size_t)(BT + BATCH) * HIDDEN];   // [t][b][H], block 0 = zeros
__device__ volatile unsigned g_sync;

// ---------------- tf32 helpers ----------------
__device__ __forceinline__ unsigned f2tf(float f) {
    unsigned u; asm("cvt.rna.tf32.f32 %0, %1;" : "=r"(u) : "f"(f)); return u;
}
__device__ __forceinline__ void mma8(float* c, unsigned a0, unsigned a1,
                                     unsigned a2, unsigned a3,
                                     unsigned b0, unsigned b1) {
    asm volatile(
        "mma.sync.aligned.m16n8k8.row.col.f32.tf32.tf32.f32 "
        "{%0,%1,%2,%3},{%4,%5,%6,%7},{%8,%9},{%0,%1,%2,%3};"
        : "+f"(c[0]), "+f"(c[1]), "+f"(c[2]), "+f"(c[3])
        : "r"(a0), "r"(a1), "r"(a2), "r"(a3), "r"(b0), "r"(b1));
}

// ---------------------------------------------------------------------------
// tf32 GEMM: C[M,N] = A[M,K] @ B[N,K]^T (+bias1+bias2), block 128x64x32.
// perm: 0 none; 1: out_row=(m&255)*64+(m>>8); 2: out_row=(m&63)*256+(m>>6).
// Requires M%128==0, N%64==0, K%32==0.
// ---------------------------------------------------------------------------
__global__ __launch_bounds__(256, 1) void gemm_tf32(
    const float* __restrict__ A, int lda,
    const float* __restrict__ B, int ldb,
    float* __restrict__ C, int ldc, int K,
    const float* __restrict__ bias1, const float* __restrict__ bias2,
    int perm)
{
    __shared__ unsigned As[128][36];
    __shared__ unsigned Bs[64][36];
    const int tid = threadIdx.x, w = tid >> 5, lane = tid & 31;
    const int g = lane >> 2, cq = lane & 3;
    const int wm = w >> 1, wn = w & 1;
    const long m0 = (long)blockIdx.x * 128, n0 = (long)blockIdx.y * 64;

    float acc[2][4][4];
#pragma unroll
    for (int i = 0; i < 2; i++)
#pragma unroll
        for (int jn = 0; jn < 4; jn++)
#pragma unroll
            for (int e = 0; e < 4; e++) acc[i][jn][e] = 0.f;

    const int srow = tid >> 3, scol = (tid & 7) * 4;

    for (int k0 = 0; k0 < K; k0 += 32) {
#pragma unroll
        for (int p = 0; p < 4; p++) {
            int r = p * 32 + srow;
            float4 v = *(const float4*)(A + (size_t)(m0 + r) * lda + k0 + scol);
            unsigned* d = &As[r][scol];
            d[0] = f2tf(v.x); d[1] = f2tf(v.y); d[2] = f2tf(v.z); d[3] = f2tf(v.w);
        }
#pragma unroll
        for (int p = 0; p < 2; p++) {
            int r = p * 32 + srow;
            float4 v = *(const float4*)(B + (size_t)(n0 + r) * ldb + k0 + scol);
            unsigned* d = &Bs[r][scol];
            d[0] = f2tf(v.x); d[1] = f2tf(v.y); d[2] = f2tf(v.z); d[3] = f2tf(v.w);
        }
        __syncthreads();
#pragma unroll
        for (int kk = 0; kk < 32; kk += 8) {
            unsigned a[2][4], b[4][2];
#pragma unroll
            for (int mi = 0; mi < 2; mi++) {
                int rb = wm * 32 + mi * 16 + g;
                a[mi][0] = As[rb][kk + cq];
                a[mi][1] = As[rb + 8][kk + cq];
                a[mi][2] = As[rb][kk + cq + 4];
                a[mi][3] = As[rb + 8][kk + cq + 4];
            }
#pragma unroll
            for (int ni = 0; ni < 4; ni++) {
                int nb = wn * 32 + ni * 8 + g;
                b[ni][0] = Bs[nb][kk + cq];
                b[ni][1] = Bs[nb][kk + cq + 4];
            }
#pragma unroll
            for (int mi = 0; mi < 2; mi++)
#pragma unroll
                for (int ni = 0; ni < 4; ni++)
                    mma8(acc[mi][ni], a[mi][0], a[mi][1], a[mi][2], a[mi][3],
                         b[ni][0], b[ni][1]);
        }
        __syncthreads();
    }

#pragma unroll
    for (int ni = 0; ni < 4; ni++) {
        long col = n0 + wn * 32 + ni * 8 + 2 * cq;
        float bv0 = 0.f, bv1 = 0.f;
        if (bias1) { bv0 += bias1[col]; bv1 += bias1[col + 1]; }
        if (bias2) { bv0 += bias2[col]; bv1 += bias2[col + 1]; }
#pragma unroll
        for (int mi = 0; mi < 2; mi++) {
            long r0 = m0 + wm * 32 + mi * 16 + g;
            long r1 = r0 + 8;
            long p0 = (perm == 1) ? (r0 & 255) * 64 + (r0 >> 8)
                    : (perm == 2) ? (r0 & 63) * 256 + (r0 >> 6) : r0;
            long p1 = (perm == 1) ? (r1 & 255) * 64 + (r1 >> 8)
                    : (perm == 2) ? (r1 & 63) * 256 + (r1 >> 6) : r1;
            *(float2*)(C + p0 * ldc + col) =
                make_float2(acc[mi][ni][0] + bv0, acc[mi][ni][1] + bv1);
            *(float2*)(C + p1 * ldc + col) =
                make_float2(acc[mi][ni][2] + bv0, acc[mi][ni][3] + bv1);
        }
    }
}

// ---------------------------------------------------------------------------
// init: zero h block 0 and the grid-sync counter (every launch/replay).
// ---------------------------------------------------------------------------
__global__ void init_kernel()
{
    int idx = blockIdx.x * blockDim.x + threadIdx.x;
    g_hh[idx] = 0.f;
    if (idx == 0) g_sync = 0;
}

// ---------------------------------------------------------------------------
// Persistent LSTM recurrence. 128 CTAs x 256 threads, all co-resident.
// CTA j owns hidden units [8j, 8j+8) -> 32 gate rows of W_hh in smem (tf32).
// Per step: tf32 mma (M=64 batch, N=32 rows, K=1024) + fused cell update,
// then release/acquire grid barrier; h_t blocks flow through L2 via g_hh.
// ---------------------------------------------------------------------------
#define WS_STRIDE 1028
#define SMEM_BYTES (32 * WS_STRIDE * 4 + 2 * 64 * 32 * 4 + 512 * 4)

__global__ __launch_bounds__(256, 1) void lstm_persistent(
    const float* __restrict__ pre, const float* __restrict__ Whh)
{
    extern __shared__ unsigned char smraw[];
    unsigned* Ws  = (unsigned*)smraw;                          // [32][1028]
    float*    Cb  = (float*)(smraw + 32 * WS_STRIDE * 4);      // [2][64][32]
    float*    csm = (float*)(smraw + 32 * WS_STRIDE * 4 + 16384); // [512]

    const int j = blockIdx.x, tid = threadIdx.x;
    const int w = tid >> 5, lane = tid & 31;
    const int g = lane >> 2, cq = lane & 3;

    // Stage this CTA's 32 W_hh rows (gate-grouped: n = gate*8 + uu) as tf32.
    for (int i4 = tid; i4 < 32 * 256; i4 += 256) {
        int n = i4 >> 8, kv = (i4 & 255) * 4;
        int grow = (n >> 3) * 1024 + 8 * j + (n & 7);
        float4 v = *(const float4*)(Whh + (size_t)grow * 1024 + kv);
        unsigned* d = Ws + n * WS_STRIDE + kv;
        d[0] = f2tf(v.x); d[1] = f2tf(v.y); d[2] = f2tf(v.z); d[3] = f2tf(v.w);
    }
    csm[tid] = 0.f; csm[tid + 256] = 0.f;
    __syncthreads();

    const int mt = w & 3, kh = w >> 2;        // warp = m-tile x K-half
    const int mbase = mt * 16, k0 = kh * 512;
    const int q0 = tid, q1 = tid + 256;       // (b,u) pairs for cell update
    const int b0i = q0 >> 3, u0i = q0 & 7, b1i = q1 >> 3, u1i = q1 & 7;

    for (int t = 0; t < SEQ; t++) {
        // prefetch pre-gates for the cell update (independent of mma)
        const float* pb0 = pre + ((size_t)t * 64 + b0i) * G4 + 8 * j + u0i;
        const float* pb1 = pre + ((size_t)t * 64 + b1i) * G4 + 8 * j + u1i;
        float pg0i = pb0[0], pg0f = pb0[1024], pg0g = pb0[2048], pg0o = pb0[3072];
        float pg1i = pb1[0], pg1f = pb1[1024], pg1g = pb1[2048], pg1o = pb1[3072];

        const float* hprev = g_hh + (size_t)t * BATCH * HIDDEN;
        float acc[4][4];
#pragma unroll
        for (int ni = 0; ni < 4; ni++)
#pragma unroll
            for (int e = 0; e < 4; e++) acc[ni][e] = 0.f;

        const float* pa0 = hprev + (size_t)(mbase + g) * 1024 + k0 + cq;
        const float* pa1 = pa0 + 8 * 1024;
        const unsigned* wbase = Ws + (size_t)g * WS_STRIDE + k0 + cq;

#pragma unroll 4
        for (int k8 = 0; k8 < 64; k8++) {
            const int o = k8 * 8;
            unsigned a0 = __float_as_uint(pa0[o]);
            unsigned a2 = __float_as_uint(pa0[o + 4]);
            unsigned a1 = __float_as_uint(pa1[o]);
            unsigned a3 = __float_as_uint(pa1[o + 4]);
            const unsigned* wb = wbase + o;
#pragma unroll
            for (int ni = 0; ni < 4; ni++) {
                unsigned b0 = wb[ni * 8 * WS_STRIDE];
                unsigned b1 = wb[ni * 8 * WS_STRIDE + 4];
                mma8(acc[ni], a0, a1, a2, a3, b0, b1);
            }
        }

        // partials -> smem (per K-half)
        float* cb = Cb + kh * 64 * 32;
#pragma unroll
        for (int ni = 0; ni < 4; ni++) {
            *(float2*)(cb + (mbase + g) * 32 + ni * 8 + 2 * cq) =
                make_float2(acc[ni][0], acc[ni][1]);
            *(float2*)(cb + (mbase + 8 + g) * 32 + ni * 8 + 2 * cq) =
                make_float2(acc[ni][2], acc[ni][3]);
        }
        __syncthreads();

        // fused cell update: reduce K-halves + pre-gates, sigmoid/tanh, write h
        {
            float gi = Cb[b0i * 32 + u0i]      + Cb[2048 + b0i * 32 + u0i]      + pg0i;
            float gf = Cb[b0i * 32 + 8 + u0i]  + Cb[2048 + b0i * 32 + 8 + u0i]  + pg0f;
            float gg = Cb[b0i * 32 + 16 + u0i] + Cb[2048 + b0i * 32 + 16 + u0i] + pg0g;
            float go = Cb[b0i * 32 + 24 + u0i] + Cb[2048 + b0i * 32 + 24 + u0i] + pg0o;
            float cc = csm[q0];
            float iv = 1.f / (1.f + __expf(-gi));
            float fv = 1.f / (1.f + __expf(-gf));
            float gv = tanhf(gg);
            float ov = 1.f / (1.f + __expf(-go));
            cc = fv * cc + iv * gv;
            csm[q0] = cc;
            float hh = ov * tanhf(cc);
            g_hh[((size_t)(t + 1) * 64 + b0i) * 1024 + 8 * j + u0i] =
                __uint_as_float(f2tf(hh));
        }
        {
            float gi = Cb[b1i * 32 + u1i]      + Cb[2048 + b1i * 32 + u1i]      + pg1i;
            float gf = Cb[b1i * 32 + 8 + u1i]  + Cb[2048 + b1i * 32 + 8 + u1i]  + pg1f;
            float gg = Cb[b1i * 32 + 16 + u1i] + Cb[2048 + b1i * 32 + 16 + u1i] + pg1g;
            float go = Cb[b1i * 32 + 24 + u1i] + Cb[2048 + b1i * 32 + 24 + u1i] + pg1o;
            float cc = csm[q1];
            float iv = 1.f / (1.f + __expf(-gi));
            float fv = 1.f / (1.f + __expf(-gf));
            float gv = tanhf(gg);
            float ov = 1.f / (1.f + __expf(-go));
            cc = fv * cc + iv * gv;
            csm[q1] = cc;
            float hh = ov * tanhf(cc);
            g_hh[((size_t)(t + 1) * 64 + b1i) * 1024 + 8 * j + u1i] =
                __uint_as_float(f2tf(hh));
        }

        // grid barrier: CTA-bar (cumulativity) + tid0 release-add / acquire-spin
        __syncthreads();
        if (tid == 0) {
            __threadfence();                       // release (cumulative via bar)
            atomicAdd((unsigned*)&g_sync, 1u);
            const unsigned target = (unsigned)NCTA * (unsigned)(t + 1);
            while (g_sync < target) {}
            __threadfence();                       // acquire
        }
        __syncthreads();
    }
}

// ---------------------------------------------------------------------------
extern "C" void kernel_launch(void* const* d_in, const int* in_sizes, int n_in,
                              void* d_out, int out_size)
{
    const float* emb  = (const float*)d_in[0];  // [64, 256, 512]
    const float* W_ih = (const float*)d_in[1];  // [4096, 512]
    const float* W_hh = (const float*)d_in[2];  // [4096, 1024]
    const float* b_ih = (const float*)d_in[3];
    const float* b_hh = (const float*)d_in[4];
    const float* W_fc = (const float*)d_in[5];  // [1024, 1024]
    const float* b_fc = (const float*)d_in[6];
    float* out = (float*)d_out;                 // [64, 256, 1024]

    float *pre, *hh;
    cudaGetSymbolAddress((void**)&pre, g_pre);
    cudaGetSymbolAddress((void**)&hh,  g_hh);

    // zero h_0 block + barrier counter (must run every replay)
    init_kernel<<<64, 1024>>>();

    // prepass: pre[t*64+b] = emb[b*256+t] @ W_ih^T + b_ih + b_hh   (perm=1)
    gemm_tf32<<<dim3(BT / 128, G4 / 64), 256>>>(
        emb, EMBED, W_ih, EMBED, pre, G4, EMBED, b_ih, b_hh, 1);

    // persistent recurrence (all 256 steps in one kernel)
    cudaFuncSetAttribute(lstm_persistent,
                         cudaFuncAttributeMaxDynamicSharedMemorySize, SMEM_BYTES);
    lstm_persistent<<<NCTA, 256, SMEM_BYTES>>>(pre, W_hh);

    // fc: out[b*256+t] = h[t*64+b] @ W_fc^T + b_fc   (perm=2)
    gemm_tf32<<<dim3(BT / 128, HIDDEN / 64), 256>>>(
        hh + (size_t)BATCH * HIDDEN, HIDDEN, W_fc, HIDDEN,
        out, HIDDEN, HIDDEN, b_fc, nullptr, 2);
}

// round 8
// speedup vs baseline: 3.3699x; 1.7735x over previous
#include <cuda_runtime.h>

#define BATCH  64
#define SEQ    256
#define EMBED  512
#define HIDDEN 1024
#define G4     4096
#define BT     (BATCH * SEQ)
#define NCTA   128

// ---------------- scratch ----------------
// packed h: [t][k8 0..127][mgroup 0..3][lane 0..31][slot 0..3]  (65536 floats per t)
__device__ __align__(256) float g_pre  [(size_t)BT * G4];
__device__ __align__(256) float g_hpack[(size_t)(SEQ + 1) * 65536];
__device__ __align__(256) float g_hist [(size_t)BT * HIDDEN];
__device__ volatile unsigned g_sync;

// ---------------- tf32 helpers ----------------
__device__ __forceinline__ unsigned f2tf(float f) {
    unsigned u; asm("cvt.rna.tf32.f32 %0, %1;" : "=r"(u) : "f"(f)); return u;
}
__device__ __forceinline__ void mma8(float* c, unsigned a0, unsigned a1,
                                     unsigned a2, unsigned a3,
                                     unsigned b0, unsigned b1) {
    asm volatile(
        "mma.sync.aligned.m16n8k8.row.col.f32.tf32.tf32.f32 "
        "{%0,%1,%2,%3},{%4,%5,%6,%7},{%8,%9},{%0,%1,%2,%3};"
        : "+f"(c[0]), "+f"(c[1]), "+f"(c[2]), "+f"(c[3])
        : "r"(a0), "r"(a1), "r"(a2), "r"(a3), "r"(b0), "r"(b1));
}

// ---------------------------------------------------------------------------
// tf32 GEMM: C[M,N] = A[M,K] @ B[N,K]^T (+bias1+bias2), block 128x64x32.
// perm: 0 none; 1: out_row=(m&255)*64+(m>>8); 2: out_row=(m&63)*256+(m>>6).
// ---------------------------------------------------------------------------
__global__ __launch_bounds__(256, 2) void gemm_tf32(
    const float* __restrict__ A, int lda,
    const float* __restrict__ B, int ldb,
    float* __restrict__ C, int ldc, int K,
    const float* __restrict__ bias1, const float* __restrict__ bias2,
    int perm)
{
    __shared__ unsigned As[128][36];
    __shared__ unsigned Bs[64][36];
    const int tid = threadIdx.x, w = tid >> 5, lane = tid & 31;
    const int g = lane >> 2, cq = lane & 3;
    const int wm = w >> 1, wn = w & 1;
    const long m0 = (long)blockIdx.x * 128, n0 = (long)blockIdx.y * 64;

    float acc[2][4][4];
#pragma unroll
    for (int i = 0; i < 2; i++)
#pragma unroll
        for (int jn = 0; jn < 4; jn++)
#pragma unroll
            for (int e = 0; e < 4; e++) acc[i][jn][e] = 0.f;

    const int srow = tid >> 3, scol = (tid & 7) * 4;

    for (int k0 = 0; k0 < K; k0 += 32) {
#pragma unroll
        for (int p = 0; p < 4; p++) {
            int r = p * 32 + srow;
            float4 v = *(const float4*)(A + (size_t)(m0 + r) * lda + k0 + scol);
            unsigned* d = &As[r][scol];
            d[0] = f2tf(v.x); d[1] = f2tf(v.y); d[2] = f2tf(v.z); d[3] = f2tf(v.w);
        }
#pragma unroll
        for (int p = 0; p < 2; p++) {
            int r = p * 32 + srow;
            float4 v = *(const float4*)(B + (size_t)(n0 + r) * ldb + k0 + scol);
            unsigned* d = &Bs[r][scol];
            d[0] = f2tf(v.x); d[1] = f2tf(v.y); d[2] = f2tf(v.z); d[3] = f2tf(v.w);
        }
        __syncthreads();
#pragma unroll
        for (int kk = 0; kk < 32; kk += 8) {
            unsigned a[2][4], b[4][2];
#pragma unroll
            for (int mi = 0; mi < 2; mi++) {
                int rb = wm * 32 + mi * 16 + g;
                a[mi][0] = As[rb][kk + cq];
                a[mi][1] = As[rb + 8][kk + cq];
                a[mi][2] = As[rb][kk + cq + 4];
                a[mi][3] = As[rb + 8][kk + cq + 4];
            }
#pragma unroll
            for (int ni = 0; ni < 4; ni++) {
                int nb = wn * 32 + ni * 8 + g;
                b[ni][0] = Bs[nb][kk + cq];
                b[ni][1] = Bs[nb][kk + cq + 4];
            }
#pragma unroll
            for (int mi = 0; mi < 2; mi++)
#pragma unroll
                for (int ni = 0; ni < 4; ni++)
                    mma8(acc[mi][ni], a[mi][0], a[mi][1], a[mi][2], a[mi][3],
                         b[ni][0], b[ni][1]);
        }
        __syncthreads();
    }

#pragma unroll
    for (int ni = 0; ni < 4; ni++) {
        long col = n0 + wn * 32 + ni * 8 + 2 * cq;
        float bv0 = 0.f, bv1 = 0.f;
        if (bias1) { bv0 += bias1[col]; bv1 += bias1[col + 1]; }
        if (bias2) { bv0 += bias2[col]; bv1 += bias2[col + 1]; }
#pragma unroll
        for (int mi = 0; mi < 2; mi++) {
            long r0 = m0 + wm * 32 + mi * 16 + g;
            long r1 = r0 + 8;
            long p0 = (perm == 1) ? (r0 & 255) * 64 + (r0 >> 8)
                    : (perm == 2) ? (r0 & 63) * 256 + (r0 >> 6) : r0;
            long p1 = (perm == 1) ? (r1 & 255) * 64 + (r1 >> 8)
                    : (perm == 2) ? (r1 & 63) * 256 + (r1 >> 6) : r1;
            *(float2*)(C + p0 * ldc + col) =
                make_float2(acc[mi][ni][0] + bv0, acc[mi][ni][1] + bv1);
            *(float2*)(C + p1 * ldc + col) =
                make_float2(acc[mi][ni][2] + bv0, acc[mi][ni][3] + bv1);
        }
    }
}

// ---------------------------------------------------------------------------
__global__ void init_kernel()
{
    int idx = blockIdx.x * blockDim.x + threadIdx.x;   // 65536 threads
    g_hpack[idx] = 0.f;                                // h_0 block (packed) = 0
    if (idx == 0) g_sync = 0;
}

// ---------------------------------------------------------------------------
// Persistent LSTM recurrence. 128 CTAs x 256 threads (1/SM, co-resident).
// CTA j owns hidden units [8j,8j+8) -> 32 gate rows (gate-grouped n=gate*8+u).
// Warps: 2 m-tiles(32 batch rows) x 4 K-splits(256). W_hh pre-packed in smem
// as B-fragments (LDS.64); h read from global in A-fragment-packed layout
// (1 coalesced LDG.128 per fragment); partial reduce + cell fused in smem.
// ---------------------------------------------------------------------------
#define P_STRIDE 34
#define SM_WP_WORDS   32768                         // 128 KB
#define SM_P_WORDS    (4 * 64 * P_STRIDE)           // 8704
#define SM_TOTAL_B    ((SM_WP_WORDS + SM_P_WORDS + 512) * 4)

__global__ __launch_bounds__(256, 1) void lstm_persistent(
    const float* __restrict__ pre, const float* __restrict__ Whh)
{
    extern __shared__ unsigned char smraw[];
    unsigned* Wp  = (unsigned*)smraw;                                 // packed B-frags
    float*    P   = (float*)(smraw + SM_WP_WORDS * 4);                // partials
    float*    csm = (float*)(smraw + (SM_WP_WORDS + SM_P_WORDS) * 4); // c state

    const int j = blockIdx.x, tid = threadIdx.x;
    const int w = tid >> 5, lane = tid & 31;
    const int g = lane >> 2, cq = lane & 3;

    // ---- one-time: pack W_hh into B-fragment order (tf32) ----
    // Wp[((k8*4 + ni)*32 + lane)*2 + h] = W[ni*1024 + 8j + (lane>>2)][k8*8 + h*4 + (lane&3)]
    for (int idx = tid; idx < SM_WP_WORDS; idx += 256) {
        int hh = idx & 1;
        int l  = (idx >> 1) & 31;
        int ni = (idx >> 6) & 3;
        int k8 = idx >> 8;
        int k  = k8 * 8 + hh * 4 + (l & 3);
        int grow = ni * 1024 + 8 * j + (l >> 2);
        Wp[idx] = f2tf(Whh[(size_t)grow * 1024 + k]);
    }
    csm[tid] = 0.f; csm[tid + 256] = 0.f;
    __syncthreads();

    const int mtw = w & 1;        // m-half: rows [mtw*32, +32)
    const int kh  = w >> 1;       // K-split: k8 range [kh*32, +32)

    // cell-update assignments (2 per thread)
    const int b0 = tid >> 3, u0 = tid & 7;
    const int b1 = (tid + 256) >> 3, u1 = u0;

    for (int t = 0; t < SEQ; t++) {
        // prefetch pre-gates (cold DRAM; consumed at end of step)
        const float* pp0 = pre + ((size_t)t * 64 + b0) * G4 + 8 * j + u0;
        const float* pp1 = pre + ((size_t)t * 64 + b1) * G4 + 8 * j + u1;
        float p0i = pp0[0], p0f = pp0[1024], p0g = pp0[2048], p0o = pp0[3072];
        float p1i = pp1[0], p1f = pp1[1024], p1g = pp1[2048], p1o = pp1[3072];

        float acc[2][4][4];
#pragma unroll
        for (int mi = 0; mi < 2; mi++)
#pragma unroll
            for (int ni = 0; ni < 4; ni++)
#pragma unroll
                for (int e = 0; e < 4; e++) acc[mi][ni][e] = 0.f;

        // A fragments: packed float4 per (k8, mgroup)
        const float4* Abase = (const float4*)(g_hpack + (size_t)t * 65536);

        float4 Abuf[2][8][2];   // [buf][k8 in chunk of 8][m16 group]
#pragma unroll
        for (int kl = 0; kl < 8; kl++)
#pragma unroll
            for (int mi = 0; mi < 2; mi++)
                Abuf[0][kl][mi] =
                    Abase[((kh * 32 + kl) * 4 + (mtw * 2 + mi)) * 32 + lane];

        for (int c = 0; c < 4; c++) {
            if (c < 3) {
                int k8b = kh * 32 + (c + 1) * 8;
#pragma unroll
                for (int kl = 0; kl < 8; kl++)
#pragma unroll
                    for (int mi = 0; mi < 2; mi++)
                        Abuf[(c + 1) & 1][kl][mi] =
                            Abase[((k8b + kl) * 4 + (mtw * 2 + mi)) * 32 + lane];
            }
            int k8b = kh * 32 + c * 8;
#pragma unroll
            for (int kl = 0; kl < 8; kl++) {
                uint2 bf[4];
#pragma unroll
                for (int ni = 0; ni < 4; ni++)
                    bf[ni] = *(const uint2*)&Wp[((k8b + kl) * 4 + ni) * 64 + lane * 2];
#pragma unroll
                for (int mi = 0; mi < 2; mi++) {
                    float4 a = Abuf[c & 1][kl][mi];
#pragma unroll
                    for (int ni = 0; ni < 4; ni++)
                        mma8(acc[mi][ni],
                             __float_as_uint(a.x), __float_as_uint(a.y),
                             __float_as_uint(a.z), __float_as_uint(a.w),
                             bf[ni].x, bf[ni].y);
                }
            }
        }

        // partials -> smem: P[(kh*64 + row)*34 + n]
#pragma unroll
        for (int mi = 0; mi < 2; mi++) {
            int r0 = mtw * 32 + mi * 16 + g;
#pragma unroll
            for (int ni = 0; ni < 4; ni++) {
                int col = ni * 8 + 2 * cq;
                *(float2*)&P[(kh * 64 + r0) * P_STRIDE + col] =
                    make_float2(acc[mi][ni][0], acc[mi][ni][1]);
                *(float2*)&P[(kh * 64 + r0 + 8) * P_STRIDE + col] =
                    make_float2(acc[mi][ni][2], acc[mi][ni][3]);
            }
        }
        __syncthreads();

        // fused cell update (2 units per thread)
#pragma unroll
        for (int q = 0; q < 2; q++) {
            int b = q ? b1 : b0, u = q ? u1 : u0;
            float pi = q ? p1i : p0i, pf = q ? p1f : p0f;
            float pg = q ? p1g : p0g, po = q ? p1o : p0o;
            float gi = pi, gf = pf, gg = pg, go = po;
#pragma unroll
            for (int kk = 0; kk < 4; kk++) {
                const float* pr = &P[(kk * 64 + b) * P_STRIDE];
                gi += pr[u]; gf += pr[8 + u]; gg += pr[16 + u]; go += pr[24 + u];
            }
            int ci = q * 256 + tid;
            float cc = csm[ci];
            float iv = 1.f / (1.f + __expf(-gi));
            float fv = 1.f / (1.f + __expf(-gf));
            float gv = tanhf(gg);
            float ov = 1.f / (1.f + __expf(-go));
            cc = fv * cc + iv * gv;
            csm[ci] = cc;
            float hv = ov * tanhf(cc);
            float hq = __uint_as_float(f2tf(hv));
            // packed write for next step's A-fragments
            int mg = b >> 4, gg2 = b & 7, hi = (b >> 3) & 1;
            int cq2 = u & 3, ch = u >> 2;
            g_hpack[(size_t)(t + 1) * 65536 + ((size_t)j * 4 + mg) * 128 +
                    (gg2 * 4 + cq2) * 4 + (hi + 2 * ch)] = hq;
            // plain write for the fc GEMM
            g_hist[((size_t)t * 64 + b) * 1024 + 8 * j + u] = hq;
        }

        // grid barrier
        __syncthreads();
        if (tid == 0) {
            __threadfence();
            atomicAdd((unsigned*)&g_sync, 1u);
            const unsigned target = (unsigned)NCTA * (unsigned)(t + 1);
            while (g_sync < target) {}
            __threadfence();
        }
        __syncthreads();
    }
}

// ---------------------------------------------------------------------------
extern "C" void kernel_launch(void* const* d_in, const int* in_sizes, int n_in,
                              void* d_out, int out_size)
{
    const float* emb  = (const float*)d_in[0];
    const float* W_ih = (const float*)d_in[1];
    const float* W_hh = (const float*)d_in[2];
    const float* b_ih = (const float*)d_in[3];
    const float* b_hh = (const float*)d_in[4];
    const float* W_fc = (const float*)d_in[5];
    const float* b_fc = (const float*)d_in[6];
    float* out = (float*)d_out;

    float *pre, *hist;
    cudaGetSymbolAddress((void**)&pre,  g_pre);
    cudaGetSymbolAddress((void**)&hist, g_hist);

    init_kernel<<<64, 1024>>>();

    // prepass: pre[t*64+b] = emb[b*256+t] @ W_ih^T + b_ih + b_hh   (perm=1)
    gemm_tf32<<<dim3(BT / 128, G4 / 64), 256>>>(
        emb, EMBED, W_ih, EMBED, pre, G4, EMBED, b_ih, b_hh, 1);

    cudaFuncSetAttribute(lstm_persistent,
                         cudaFuncAttributeMaxDynamicSharedMemorySize, SM_TOTAL_B);
    lstm_persistent<<<NCTA, 256, SM_TOTAL_B>>>(pre, W_hh);

    // fc: out[b*256+t] = hist[t*64+b] @ W_fc^T + b_fc   (perm=2)
    gemm_tf32<<<dim3(BT / 128, HIDDEN / 64), 256>>>(
        hist, HIDDEN, W_fc, HIDDEN, out, HIDDEN, HIDDEN, b_fc, nullptr, 2);
}

// round 10
// speedup vs baseline: 3.7042x; 1.0992x over previous
#include <cuda_runtime.h>

#define BATCH  64
#define SEQ    256
#define EMBED  512
#define HIDDEN 1024
#define G4     4096
#define BT     (BATCH * SEQ)
#define NCTA   128

// ---------------- scratch ----------------
// packed h: [t][k8 0..127][mgroup 0..3][lane 0..31][slot 0..3]  (65536 floats per t)
__device__ __align__(256) float g_pre  [(size_t)BT * G4];
__device__ __align__(256) float g_hpack[(size_t)(SEQ + 1) * 65536];
__device__ __align__(256) float g_hist [(size_t)BT * HIDDEN];
__device__ unsigned g_sync;

// ---------------- tf32 helpers ----------------
__device__ __forceinline__ unsigned f2tf(float f) {
    unsigned u; asm("cvt.rna.tf32.f32 %0, %1;" : "=r"(u) : "f"(f)); return u;
}
__device__ __forceinline__ void mma8(float* c, unsigned a0, unsigned a1,
                                     unsigned a2, unsigned a3,
                                     unsigned b0, unsigned b1) {
    asm volatile(
        "mma.sync.aligned.m16n8k8.row.col.f32.tf32.tf32.f32 "
        "{%0,%1,%2,%3},{%4,%5,%6,%7},{%8,%9},{%0,%1,%2,%3};"
        : "+f"(c[0]), "+f"(c[1]), "+f"(c[2]), "+f"(c[3])
        : "r"(a0), "r"(a1), "r"(a2), "r"(a3), "r"(b0), "r"(b1));
}

// ---------------------------------------------------------------------------
// tf32 GEMM: C[M,N] = A[M,K] @ B[N,K]^T (+bias1+bias2), block 128x128x32,
// 8 warps as 2(m) x 4(n), warp tile 64x32 (10.7 FLOP/B of smem -> crossbar
// no longer binds the tensor pipe).
// perm: 0 none; 1: out_row=(m&255)*64+(m>>8); 2: out_row=(m&63)*256+(m>>6).
// Requires M%128==0, N%128==0, K%32==0.
// ---------------------------------------------------------------------------
__global__ __launch_bounds__(256, 2) void gemm_tf32(
    const float* __restrict__ A, int lda,
    const float* __restrict__ B, int ldb,
    float* __restrict__ C, int ldc, int K,
    const float* __restrict__ bias1, const float* __restrict__ bias2,
    int perm)
{
    __shared__ unsigned As[128][36];
    __shared__ unsigned Bs[128][36];
    const int tid = threadIdx.x, w = tid >> 5, lane = tid & 31;
    const int g = lane >> 2, cq = lane & 3;
    const int wm = w >> 2;          // 0..1 : 64 m-rows
    const int wn = w & 3;           // 0..3 : 32 n-cols
    const long m0 = (long)blockIdx.x * 128, n0 = (long)blockIdx.y * 128;

    float acc[4][4][4];
#pragma unroll
    for (int mi = 0; mi < 4; mi++)
#pragma unroll
        for (int ni = 0; ni < 4; ni++)
#pragma unroll
            for (int e = 0; e < 4; e++) acc[mi][ni][e] = 0.f;

    const int srow = tid >> 3, scol = (tid & 7) * 4;

    for (int k0 = 0; k0 < K; k0 += 32) {
#pragma unroll
        for (int p = 0; p < 4; p++) {
            int r = p * 32 + srow;
            float4 v = *(const float4*)(A + (size_t)(m0 + r) * lda + k0 + scol);
            unsigned* d = &As[r][scol];
            d[0] = f2tf(v.x); d[1] = f2tf(v.y); d[2] = f2tf(v.z); d[3] = f2tf(v.w);
        }
#pragma unroll
        for (int p = 0; p < 4; p++) {
            int r = p * 32 + srow;
            float4 v = *(const float4*)(B + (size_t)(n0 + r) * ldb + k0 + scol);
            unsigned* d = &Bs[r][scol];
            d[0] = f2tf(v.x); d[1] = f2tf(v.y); d[2] = f2tf(v.z); d[3] = f2tf(v.w);
        }
        __syncthreads();
#pragma unroll
        for (int kk = 0; kk < 32; kk += 8) {
            unsigned a[4][4], b[4][2];
#pragma unroll
            for (int mi = 0; mi < 4; mi++) {
                int rb = wm * 64 + mi * 16 + g;
                a[mi][0] = As[rb][kk + cq];
                a[mi][1] = As[rb + 8][kk + cq];
                a[mi][2] = As[rb][kk + cq + 4];
                a[mi][3] = As[rb + 8][kk + cq + 4];
            }
#pragma unroll
            for (int ni = 0; ni < 4; ni++) {
                int nb = wn * 32 + ni * 8 + g;
                b[ni][0] = Bs[nb][kk + cq];
                b[ni][1] = Bs[nb][kk + cq + 4];
            }
#pragma unroll
            for (int mi = 0; mi < 4; mi++)
#pragma unroll
                for (int ni = 0; ni < 4; ni++)
                    mma8(acc[mi][ni], a[mi][0], a[mi][1], a[mi][2], a[mi][3],
                         b[ni][0], b[ni][1]);
        }
        __syncthreads();
    }

#pragma unroll
    for (int ni = 0; ni < 4; ni++) {
        long col = n0 + wn * 32 + ni * 8 + 2 * cq;
        float bv0 = 0.f, bv1 = 0.f;
        if (bias1) { bv0 += bias1[col]; bv1 += bias1[col + 1]; }
        if (bias2) { bv0 += bias2[col]; bv1 += bias2[col + 1]; }
#pragma unroll
        for (int mi = 0; mi < 4; mi++) {
            long r0 = m0 + wm * 64 + mi * 16 + g;
            long r1 = r0 + 8;
            long p0 = (perm == 1) ? (r0 & 255) * 64 + (r0 >> 8)
                    : (perm == 2) ? (r0 & 63) * 256 + (r0 >> 6) : r0;
            long p1 = (perm == 1) ? (r1 & 255) * 64 + (r1 >> 8)
                    : (perm == 2) ? (r1 & 63) * 256 + (r1 >> 6) : r1;
            *(float2*)(C + p0 * ldc + col) =
                make_float2(acc[mi][ni][0] + bv0, acc[mi][ni][1] + bv1);
            *(float2*)(C + p1 * ldc + col) =
                make_float2(acc[mi][ni][2] + bv0, acc[mi][ni][3] + bv1);
        }
    }
}

// ---------------------------------------------------------------------------
__global__ void init_kernel()
{
    int idx = blockIdx.x * blockDim.x + threadIdx.x;   // 65536 threads
    g_hpack[idx] = 0.f;                                // h_0 block (packed) = 0
    if (idx == 0) g_sync = 0;
}

// ---------------------------------------------------------------------------
// Persistent LSTM recurrence. 128 CTAs x 256 threads (1/SM, co-resident).
// CTA j owns hidden units [8j,8j+8) -> 32 gate rows (gate-grouped n=gate*8+u).
// Warps: 2 m-tiles(32 batch rows) x 4 K-splits(256). W_hh pre-packed in smem
// as B-fragments (LDS.64); h read from global in A-fragment-packed layout
// (1 coalesced LDG.128 per fragment); partial reduce + cell fused in smem.
// Grid barrier: red.release (no-return, fast at LTS) + ld.acquire poll — no
// L1 flush needed since h/pre addresses are fresh every step.
// ---------------------------------------------------------------------------
#define P_STRIDE 34
#define SM_WP_WORDS   32768                         // 128 KB
#define SM_P_WORDS    (4 * 64 * P_STRIDE)           // 8704
#define SM_TOTAL_B    ((SM_WP_WORDS + SM_P_WORDS + 512) * 4)

__global__ __launch_bounds__(256, 1) void lstm_persistent(
    const float* __restrict__ pre, const float* __restrict__ Whh)
{
    extern __shared__ unsigned char smraw[];
    unsigned* Wp  = (unsigned*)smraw;                                 // packed B-frags
    float*    P   = (float*)(smraw + SM_WP_WORDS * 4);                // partials
    float*    csm = (float*)(smraw + (SM_WP_WORDS + SM_P_WORDS) * 4); // c state

    const int j = blockIdx.x, tid = threadIdx.x;
    const int w = tid >> 5, lane = tid & 31;
    const int g = lane >> 2, cq = lane & 3;

    // ---- one-time: pack W_hh into B-fragment order (tf32) ----
    for (int idx = tid; idx < SM_WP_WORDS; idx += 256) {
        int hh = idx & 1;
        int l  = (idx >> 1) & 31;
        int ni = (idx >> 6) & 3;
        int k8 = idx >> 8;
        int k  = k8 * 8 + hh * 4 + (l & 3);
        int grow = ni * 1024 + 8 * j + (l >> 2);
        Wp[idx] = f2tf(Whh[(size_t)grow * 1024 + k]);
    }
    csm[tid] = 0.f; csm[tid + 256] = 0.f;
    __syncthreads();

    const int mtw = w & 1;        // m-half: rows [mtw*32, +32)
    const int kh  = w >> 1;       // K-split: k8 range [kh*32, +32)

    const int b0 = tid >> 3, u0 = tid & 7;
    const int b1 = (tid + 256) >> 3, u1 = u0;

    unsigned* syncp = &g_sync;

    for (int t = 0; t < SEQ; t++) {
        // prefetch pre-gates (cold DRAM; consumed at end of step)
        const float* pp0 = pre + ((size_t)t * 64 + b0) * G4 + 8 * j + u0;
        const float* pp1 = pre + ((size_t)t * 64 + b1) * G4 + 8 * j + u1;
        float p0i = pp0[0], p0f = pp0[1024], p0g = pp0[2048], p0o = pp0[3072];
        float p1i = pp1[0], p1f = pp1[1024], p1g = pp1[2048], p1o = pp1[3072];

        float acc[2][4][4];
#pragma unroll
        for (int mi = 0; mi < 2; mi++)
#pragma unroll
            for (int ni = 0; ni < 4; ni++)
#pragma unroll
                for (int e = 0; e < 4; e++) acc[mi][ni][e] = 0.f;

        const float4* Abase = (const float4*)(g_hpack + (size_t)t * 65536);

        float4 Abuf[2][8][2];
#pragma unroll
        for (int kl = 0; kl < 8; kl++)
#pragma unroll
            for (int mi = 0; mi < 2; mi++)
                Abuf[0][kl][mi] =
                    Abase[((kh * 32 + kl) * 4 + (mtw * 2 + mi)) * 32 + lane];

        for (int c = 0; c < 4; c++) {
            if (c < 3) {
                int k8b = kh * 32 + (c + 1) * 8;
#pragma unroll
                for (int kl = 0; kl < 8; kl++)
#pragma unroll
                    for (int mi = 0; mi < 2; mi++)
                        Abuf[(c + 1) & 1][kl][mi] =
                            Abase[((k8b + kl) * 4 + (mtw * 2 + mi)) * 32 + lane];
            }
            int k8b = kh * 32 + c * 8;
#pragma unroll
            for (int kl = 0; kl < 8; kl++) {
                uint2 bf[4];
#pragma unroll
                for (int ni = 0; ni < 4; ni++)
                    bf[ni] = *(const uint2*)&Wp[((k8b + kl) * 4 + ni) * 64 + lane * 2];
#pragma unroll
                for (int mi = 0; mi < 2; mi++) {
                    float4 a = Abuf[c & 1][kl][mi];
#pragma unroll
                    for (int ni = 0; ni < 4; ni++)
                        mma8(acc[mi][ni],
                             __float_as_uint(a.x), __float_as_uint(a.y),
                             __float_as_uint(a.z), __float_as_uint(a.w),
                             bf[ni].x, bf[ni].y);
                }
            }
        }

        // partials -> smem
#pragma unroll
        for (int mi = 0; mi < 2; mi++) {
            int r0 = mtw * 32 + mi * 16 + g;
#pragma unroll
            for (int ni = 0; ni < 4; ni++) {
                int col = ni * 8 + 2 * cq;
                *(float2*)&P[(kh * 64 + r0) * P_STRIDE + col] =
                    make_float2(acc[mi][ni][0], acc[mi][ni][1]);
                *(float2*)&P[(kh * 64 + r0 + 8) * P_STRIDE + col] =
                    make_float2(acc[mi][ni][2], acc[mi][ni][3]);
            }
        }
        __syncthreads();

        // fused cell update (2 units per thread)
#pragma unroll
        for (int q = 0; q < 2; q++) {
            int b = q ? b1 : b0, u = q ? u1 : u0;
            float pi = q ? p1i : p0i, pf = q ? p1f : p0f;
            float pg = q ? p1g : p0g, po = q ? p1o : p0o;
            float gi = pi, gf = pf, gg = pg, go = po;
#pragma unroll
            for (int kk = 0; kk < 4; kk++) {
                const float* pr = &P[(kk * 64 + b) * P_STRIDE];
                gi += pr[u]; gf += pr[8 + u]; gg += pr[16 + u]; go += pr[24 + u];
            }
            int ci = q * 256 + tid;
            float cc = csm[ci];
            float iv = 1.f / (1.f + __expf(-gi));
            float fv = 1.f / (1.f + __expf(-gf));
            float gv = tanhf(gg);
            float ov = 1.f / (1.f + __expf(-go));
            cc = fv * cc + iv * gv;
            csm[ci] = cc;
            float hv = ov * tanhf(cc);
            float hq = __uint_as_float(f2tf(hv));
            int mg = b >> 4, gg2 = b & 7, hi = (b >> 3) & 1;
            int cq2 = u & 3, ch = u >> 2;
            g_hpack[(size_t)(t + 1) * 65536 + ((size_t)j * 4 + mg) * 128 +
                    (gg2 * 4 + cq2) * 4 + (hi + 2 * ch)] = hq;
            g_hist[((size_t)t * 64 + b) * 1024 + 8 * j + u] = hq;
        }

        // grid barrier: bar + red.release arrive, acquire-load poll
        __syncthreads();
        if (tid == 0) {
            asm volatile("red.release.gpu.global.add.u32 [%0], 1;"
                         :: "l"(syncp) : "memory");
            const unsigned target = (unsigned)NCTA * (unsigned)(t + 1);
            unsigned v;
            do {
                asm volatile("ld.acquire.gpu.global.u32 %0, [%1];"
                             : "=r"(v) : "l"(syncp) : "memory");
            } while (v < target);
        }
        __syncthreads();
    }
}

// ---------------------------------------------------------------------------
extern "C" void kernel_launch(void* const* d_in, const int* in_sizes, int n_in,
                              void* d_out, int out_size)
{
    const float* emb  = (const float*)d_in[0];
    const float* W_ih = (const float*)d_in[1];
    const float* W_hh = (const float*)d_in[2];
    const float* b_ih = (const float*)d_in[3];
    const float* b_hh = (const float*)d_in[4];
    const float* W_fc = (const float*)d_in[5];
    const float* b_fc = (const float*)d_in[6];
    float* out = (float*)d_out;

    float *pre, *hist;
    cudaGetSymbolAddress((void**)&pre,  g_pre);
    cudaGetSymbolAddress((void**)&hist, g_hist);

    init_kernel<<<64, 1024>>>();

    // prepass: pre[t*64+b] = emb[b*256+t] @ W_ih^T + b_ih + b_hh   (perm=1)
    gemm_tf32<<<dim3(BT / 128, G4 / 128), 256>>>(
        emb, EMBED, W_ih, EMBED, pre, G4, EMBED, b_ih, b_hh, 1);

    cudaFuncSetAttribute(lstm_persistent,
                         cudaFuncAttributeMaxDynamicSharedMemorySize, SM_TOTAL_B);
    lstm_persistent<<<NCTA, 256, SM_TOTAL_B>>>(pre, W_hh);

    // fc: out[b*256+t] = hist[t*64+b] @ W_fc^T + b_fc   (perm=2)
    gemm_tf32<<<dim3(BT / 128, HIDDEN / 128), 256>>>(
        hist, HIDDEN, W_fc, HIDDEN, out, HIDDEN, HIDDEN, b_fc, nullptr, 2);
}